// round 13
// baseline (speedup 1.0000x reference)
#include <cuda_runtime.h>
#include <math.h>
#include <stdint.h>

#define DM   1024
#define DI   2048
#define DTR  64
#define NS   16
#define BB   4
#define LL   1024
#define NT   (BB*LL)

// ---------------- scratch ----------------------------------------------------
__device__ __align__(16) float g_xr  [(size_t)NT * 2 * DI];
__device__ __align__(16) float g_xs  [(size_t)NT * DI];
__device__ __align__(16) float g_xdbl[(size_t)NT * 96];
__device__ __align__(16) float g_delta[(size_t)NT * DI];
__device__ __align__(16) float g_yg  [(size_t)NT * DI];

// ---------------- helpers -----------------------------------------------------
__device__ __forceinline__ float ex2_approx(float x) {
    float y; asm("ex2.approx.f32 %0, %1;" : "=f"(y) : "f"(x)); return y;
}
__device__ __forceinline__ float tf32_rn(float x) {
    float r; asm("cvt.rna.tf32.f32 %0, %1;" : "=f"(r) : "f"(x)); return r;
}
__device__ __forceinline__ void mma_tf32(float* c, const uint32_t* a, const uint32_t* b) {
    asm volatile(
        "mma.sync.aligned.m16n8k8.row.col.f32.tf32.tf32.f32 "
        "{%0,%1,%2,%3}, {%4,%5,%6,%7}, {%8,%9}, {%0,%1,%2,%3};"
        : "+f"(c[0]), "+f"(c[1]), "+f"(c[2]), "+f"(c[3])
        : "r"(a[0]), "r"(a[1]), "r"(a[2]), "r"(a[3]), "r"(b[0]), "r"(b[1]));
}

// ---------------- TF32 mma.sync GEMM:  C[M,N] = A[M,K] * B[N,K]^T -------------
// BM=BN=128, BK=32, 3-stage cp.async, 128 threads: 4 warps of 64x64 (2M x 2N).
// smem 110.6KB -> 2 CTAs/SM. (Best measured config under current environment.)
// RNDA/RNDB: round A/B fragments to tf32 in-register (raw fp32 operands OK;
// bitwise-identical to pre-rounding the operand in memory).
// EPI: 0 none, 1 softplus(x+bias[n]), 3 atomicAdd (split-K; NGUARD=valid N)
template<int EPI, int NGUARD, int RNDA, int RNDB>
__global__ void __launch_bounds__(128, 2) gemm_mma(
    const float* __restrict__ A, const float* __restrict__ B,
    const float* __restrict__ bias, float* __restrict__ C,
    int K, int lda, int ldb, int ldc)
{
    constexpr int ST = 3;
    constexpr int P  = 36;                 // smem row pitch (floats)
    constexpr int ATILE = 128 * P;
    constexpr int BTILE = 128 * P;
    extern __shared__ float sm[];
    float* As = sm;
    float* Bs = sm + ST * ATILE;

    const int tid  = threadIdx.x;
    const int wid  = tid >> 5, lane = tid & 31;
    const int g    = lane >> 2, q = lane & 3;
    const int bm   = blockIdx.y * 128;
    const int bn   = blockIdx.x * 128;
    const int T    = K >> 5;
    const int mbase = (wid & 1) * 64;
    const int nbase = (wid >> 1) * 64;

    const float* Ab = A + (size_t)bm * lda + (size_t)blockIdx.z * K;
    const float* Bb = B + (size_t)bn * ldb + (size_t)blockIdx.z * K;

    auto load_tile = [&](int st, int t) {
        float* as = As + st * ATILE;
        float* bs = Bs + st * BTILE;
        #pragma unroll
        for (int i = 0; i < 8; ++i) {
            int c = tid + i * 128;
            int r = c >> 3, col = (c & 7) * 4;
            const float* src = Ab + (size_t)r * lda + t * 32 + col;
            uint32_t dst = (uint32_t)__cvta_generic_to_shared(as + r * P + col);
            asm volatile("cp.async.cg.shared.global [%0], [%1], 16;"
                         :: "r"(dst), "l"(src));
        }
        #pragma unroll
        for (int i = 0; i < 8; ++i) {
            int c = tid + i * 128;
            int r = c >> 3, col = (c & 7) * 4;
            uint32_t dst = (uint32_t)__cvta_generic_to_shared(bs + r * P + col);
            if (NGUARD && (bn + r) >= NGUARD) {
                asm volatile("cp.async.cg.shared.global [%0], [%1], 16, 0;"
                             :: "r"(dst), "l"(Bb));
            } else {
                const float* src = Bb + (size_t)r * ldb + t * 32 + col;
                asm volatile("cp.async.cg.shared.global [%0], [%1], 16;"
                             :: "r"(dst), "l"(src));
            }
        }
    };

    float c[4][8][4];
    #pragma unroll
    for (int t = 0; t < 4; ++t)
        #pragma unroll
        for (int j = 0; j < 8; ++j)
            #pragma unroll
            for (int i = 0; i < 4; ++i) c[t][j][i] = 0.f;

    #pragma unroll
    for (int s = 0; s < ST - 1; ++s) {
        if (s < T) load_tile(s, s);
        asm volatile("cp.async.commit_group;");
    }

    int cs = 0, ls = 2;
    for (int t = 0; t < T; ++t) {
        asm volatile("cp.async.wait_group 1;");
        __syncthreads();
        const float* as0 = As + cs * ATILE;
        const float* bs0 = Bs + cs * BTILE;
        #pragma unroll
        for (int k8 = 0; k8 < 4; ++k8) {
            const int k0 = k8 * 8 + q;
            uint32_t b[8][2];
            #pragma unroll
            for (int j = 0; j < 8; ++j) {
                const float* bp = bs0 + (nbase + j * 8 + g) * P + k0;
                if (RNDB) {
                    b[j][0] = __float_as_uint(tf32_rn(bp[0]));
                    b[j][1] = __float_as_uint(tf32_rn(bp[4]));
                } else {
                    b[j][0] = __float_as_uint(bp[0]);
                    b[j][1] = __float_as_uint(bp[4]);
                }
            }
            #pragma unroll
            for (int tt = 0; tt < 4; ++tt) {
                uint32_t a[4];
                const float* ap = as0 + (mbase + tt * 16 + g) * P + k0;
                if (RNDA) {
                    a[0] = __float_as_uint(tf32_rn(ap[0]));
                    a[1] = __float_as_uint(tf32_rn(ap[8 * P]));
                    a[2] = __float_as_uint(tf32_rn(ap[4]));
                    a[3] = __float_as_uint(tf32_rn(ap[8 * P + 4]));
                } else {
                    a[0] = __float_as_uint(ap[0]);
                    a[1] = __float_as_uint(ap[8 * P]);
                    a[2] = __float_as_uint(ap[4]);
                    a[3] = __float_as_uint(ap[8 * P + 4]);
                }
                #pragma unroll
                for (int j = 0; j < 8; ++j)
                    mma_tf32(c[tt][j], a, b[j]);
            }
        }
        const int kt = t + ST - 1;
        if (kt < T) load_tile(ls, kt);
        asm volatile("cp.async.commit_group;");
        cs = (cs == 2) ? 0 : cs + 1;
        ls = (ls == 2) ? 0 : ls + 1;
    }

    // epilogue
    #pragma unroll
    for (int tt = 0; tt < 4; ++tt) {
        const int r0 = bm + mbase + tt * 16 + g;
        #pragma unroll
        for (int j = 0; j < 8; ++j) {
            const int col = bn + nbase + j * 8 + q * 2;
            float v0 = c[tt][j][0], v1 = c[tt][j][1];
            float v2 = c[tt][j][2], v3 = c[tt][j][3];
            if (EPI == 1) {
                float b0 = bias[col], b1 = bias[col + 1];
                v0 += b0; v1 += b1; v2 += b0; v3 += b1;
                v0 = (v0 > 20.f) ? v0 : log1pf(__expf(v0));
                v1 = (v1 > 20.f) ? v1 : log1pf(__expf(v1));
                v2 = (v2 > 20.f) ? v2 : log1pf(__expf(v2));
                v3 = (v3 > 20.f) ? v3 : log1pf(__expf(v3));
            }
            if (EPI == 3) {
                if (!NGUARD || col < NGUARD) {
                    atomicAdd(&C[(size_t)r0 * ldc + col], v0);
                    atomicAdd(&C[(size_t)r0 * ldc + col + 1], v1);
                    atomicAdd(&C[(size_t)(r0 + 8) * ldc + col], v2);
                    atomicAdd(&C[(size_t)(r0 + 8) * ldc + col + 1], v3);
                }
            } else {
                float2 p0 = make_float2(v0, v1);
                float2 p1 = make_float2(v2, v3);
                *(float2*)&C[(size_t)r0 * ldc + col] = p0;
                *(float2*)&C[(size_t)(r0 + 8) * ldc + col] = p1;
            }
        }
    }
}

// ---------------- causal depthwise conv1d (width 4) + SiLU (+tf32) ------------
__global__ void conv_silu_kernel(const float* __restrict__ conv_w,
                                 const float* __restrict__ conv_b)
{
    int idx = blockIdx.x * blockDim.x + threadIdx.x;
    int d  = idx & (DI - 1);
    int bl = idx >> 11;
    int l  = bl & (LL - 1);
    float w0 = conv_w[d * 4 + 0], w1 = conv_w[d * 4 + 1];
    float w2 = conv_w[d * 4 + 2], w3 = conv_w[d * 4 + 3];
    const float* col = g_xr + (size_t)bl * (2 * DI) + d;
    float s = conv_b[d];
    if (l >= 3) s = fmaf(w0, col[-(3 * 2 * DI)], s);
    if (l >= 2) s = fmaf(w1, col[-(2 * 2 * DI)], s);
    if (l >= 1) s = fmaf(w2, col[-(1 * 2 * DI)], s);
    s = fmaf(w3, col[0], s);
    g_xs[idx] = tf32_rn(s / (1.f + __expf(-s)));
}

// ---------------- selective scan + D skip + gating ----------------------------
#define SC_DPB 32
#define SC_CH  64
__global__ void __launch_bounds__(256) scan_kernel(
    const float* __restrict__ A_log, const float* __restrict__ Dp)
{
    __shared__ float s_d[SC_CH][SC_DPB];
    __shared__ float s_u[SC_CH][SC_DPB];
    __shared__ float s_B[SC_CH][16];
    __shared__ float s_C[SC_CH][16];
    __shared__ float s_y[SC_CH][SC_DPB];
    const int b   = blockIdx.y;
    const int d0  = blockIdx.x * SC_DPB;
    const int tid = threadIdx.x;
    const int dl  = tid >> 3;
    const int tq  = tid & 7;
    const int d   = d0 + dl;
    const int n0  = tq * 2;

    const float LOG2E = 1.4426950408889634f;
    float a20 = -expf(A_log[d * NS + n0 + 0]) * LOG2E;
    float a21 = -expf(A_log[d * NS + n0 + 1]) * LOG2E;
    float Dv  = Dp[d];
    float h0 = 0.f, h1 = 0.f;

    for (int l0 = 0; l0 < LL; l0 += SC_CH) {
        for (int i = tid; i < SC_CH * SC_DPB; i += 256) {
            int li = i >> 5, dd = i & 31;
            size_t gg = ((size_t)(b * LL + l0 + li)) * DI + d0 + dd;
            s_d[li][dd] = g_delta[gg];
            s_u[li][dd] = g_xs[gg];
        }
        for (int i = tid; i < SC_CH * 16; i += 256) {
            int li = i >> 4, nn = i & 15;
            const float* row = g_xdbl + ((size_t)(b * LL + l0 + li)) * 96;
            s_B[li][nn] = row[64 + nn];
            s_C[li][nn] = row[80 + nn];
        }
        __syncthreads();
        #pragma unroll 4
        for (int li = 0; li < SC_CH; ++li) {
            float dv = s_d[li][dl];
            float uv = s_u[li][dl];
            float du = dv * uv;
            float dA0 = ex2_approx(dv * a20);
            float dA1 = ex2_approx(dv * a21);
            h0 = fmaf(dA0, h0, du * s_B[li][n0 + 0]);
            h1 = fmaf(dA1, h1, du * s_B[li][n0 + 1]);
            float acc = fmaf(h0, s_C[li][n0 + 0], h1 * s_C[li][n0 + 1]);
            acc += __shfl_xor_sync(0xffffffffu, acc, 1);
            acc += __shfl_xor_sync(0xffffffffu, acc, 2);
            acc += __shfl_xor_sync(0xffffffffu, acc, 4);
            if (tq == 0) s_y[li][dl] = fmaf(uv, Dv, acc);
        }
        __syncthreads();
        for (int i = tid; i < SC_CH * SC_DPB; i += 256) {
            int li = i >> 5, dd = i & 31;
            size_t bl = (size_t)(b * LL + l0 + li);
            float r  = g_xr[bl * (2 * DI) + DI + d0 + dd];
            float sr = r / (1.f + __expf(-r));
            g_yg[bl * DI + d0 + dd] = tf32_rn(s_y[li][dd] * sr);
        }
    }
}

// ---------------- launch ------------------------------------------------------
extern "C" void kernel_launch(void* const* d_in, const int* in_sizes, int n_in,
                              void* d_out, int out_size)
{
    (void)in_sizes; (void)n_in; (void)out_size;
    const float* x      = (const float*)d_in[0];
    const float* W_in   = (const float*)d_in[1];
    const float* conv_w = (const float*)d_in[2];
    const float* conv_b = (const float*)d_in[3];
    const float* W_x    = (const float*)d_in[4];
    const float* W_dt   = (const float*)d_in[5];
    const float* b_dt   = (const float*)d_in[6];
    const float* A_log  = (const float*)d_in[7];
    const float* Dp     = (const float*)d_in[8];
    const float* W_out  = (const float*)d_in[9];
    float* out = (float*)d_out;

    float *p_xr, *p_xs, *p_xdbl, *p_delta, *p_yg;
    cudaGetSymbolAddress((void**)&p_xr,    g_xr);
    cudaGetSymbolAddress((void**)&p_xs,    g_xs);
    cudaGetSymbolAddress((void**)&p_xdbl,  g_xdbl);
    cudaGetSymbolAddress((void**)&p_delta, g_delta);
    cudaGetSymbolAddress((void**)&p_yg,    g_yg);

    const int SMEM = 3 * (128 + 128) * 36 * 4;   // 110592 bytes -> 2 CTAs/SM
    cudaFuncSetAttribute(gemm_mma<0, 0, 1, 1>,  cudaFuncAttributeMaxDynamicSharedMemorySize, SMEM);
    cudaFuncSetAttribute(gemm_mma<0, 0, 0, 1>,  cudaFuncAttributeMaxDynamicSharedMemorySize, SMEM);
    cudaFuncSetAttribute(gemm_mma<1, 0, 1, 1>,  cudaFuncAttributeMaxDynamicSharedMemorySize, SMEM);
    cudaFuncSetAttribute(gemm_mma<3, 96, 0, 1>, cudaFuncAttributeMaxDynamicSharedMemorySize, SMEM);

    // zero the split-K accumulator
    cudaMemsetAsync(p_xdbl, 0, (size_t)NT * 96 * sizeof(float));

    // 1) xr = x @ W_in^T   (A and B rounded in-register; no pre-rounding pass)
    gemm_mma<0, 0, 1, 1><<<dim3(32, 32, 1), 128, SMEM>>>(
        x, W_in, nullptr, p_xr, DM, DM, DM, 2 * DI);

    // 2) xs = tf32(silu(causal dwconv(xr[:, :DI])))
    conv_silu_kernel<<<(NT * DI) / 256, 256>>>(conv_w, conv_b);

    // 3) x_dbl = xs @ W_x^T  split-K=8, atomicAdd  -> [4096,96]
    gemm_mma<3, 96, 0, 1><<<dim3(1, 32, 8), 128, SMEM>>>(
        p_xs, W_x, nullptr, p_xdbl, DI / 8, DI, DI, 96);

    // 4) delta = softplus(x_dbl[:, :64] @ W_dt^T + b_dt)  (A,B rounded in-reg)
    gemm_mma<1, 0, 1, 1><<<dim3(16, 32, 1), 128, SMEM>>>(
        p_xdbl, W_dt, b_dt, p_delta, DTR, 96, DTR, DI);

    // 5) selective scan (+D skip, *silu(res), tf32 round) -> g_yg
    scan_kernel<<<dim3(DI / SC_DPB, BB), 256>>>(A_log, Dp);

    // 6) out = yg @ W_out^T  (yg pre-rounded by scan; B rounded in-register)
    gemm_mma<0, 0, 0, 1><<<dim3(8, 32, 1), 128, SMEM>>>(
        p_yg, W_out, nullptr, out, DI, DI, DI, DM);
}

// round 14
// speedup vs baseline: 1.0467x; 1.0467x over previous
#include <cuda_runtime.h>
#include <math.h>
#include <stdint.h>

#define DM   1024
#define DI   2048
#define DTR  64
#define NS   16
#define BB   4
#define LL   1024
#define NT   (BB*LL)

// ---------------- scratch ----------------------------------------------------
__device__ __align__(16) float g_xr  [(size_t)NT * 2 * DI];
__device__ __align__(16) float g_xs  [(size_t)NT * DI];
__device__ __align__(16) float g_xdbl[(size_t)NT * 96];
__device__ __align__(16) float g_delta[(size_t)NT * DI];
__device__ __align__(16) float g_yg  [(size_t)NT * DI];
__device__ __align__(16) float g_wi  [(size_t)2 * DI * DM];
__device__ __align__(16) float g_wx  [(size_t)96 * DI];
__device__ __align__(16) float g_wdt [(size_t)DI * DTR];
__device__ __align__(16) float g_wo  [(size_t)DM * DI];

// ---------------- helpers -----------------------------------------------------
__device__ __forceinline__ float ex2_approx(float x) {
    float y; asm("ex2.approx.f32 %0, %1;" : "=f"(y) : "f"(x)); return y;
}
__device__ __forceinline__ float tf32_rn(float x) {
    float r; asm("cvt.rna.tf32.f32 %0, %1;" : "=f"(r) : "f"(x)); return r;
}
__device__ __forceinline__ float softplus_fast(float v) {
    // fast softplus: MUFU ex2/lg2 path; rel err ~1e-6, invisible under tf32 noise
    return (v > 20.f) ? v : __logf(1.f + __expf(v));
}
__device__ __forceinline__ void mma_tf32(float* c, const uint32_t* a, const uint32_t* b) {
    asm volatile(
        "mma.sync.aligned.m16n8k8.row.col.f32.tf32.tf32.f32 "
        "{%0,%1,%2,%3}, {%4,%5,%6,%7}, {%8,%9}, {%0,%1,%2,%3};"
        : "+f"(c[0]), "+f"(c[1]), "+f"(c[2]), "+f"(c[3])
        : "r"(a[0]), "r"(a[1]), "r"(a[2]), "r"(a[3]), "r"(b[0]), "r"(b[1]));
}

// ---------------- TF32 mma.sync GEMM:  C[M,N] = A[M,K] * B[N,K]^T -------------
// BM=BN=128, BK=32, 3-stage cp.async, 128 threads: 4 warps of 64x64 (2M x 2N).
// smem 110.6KB -> 2 CTAs/SM. (Best measured config under current environment.)
// RNDA=1: round A fragments to tf32 in-register (A may be raw fp32).
// B (weights) must be pre-rounded.
// EPI: 0 none, 1 fast-softplus(x+bias[n]), 3 atomicAdd (split-K; NGUARD=valid N)
template<int EPI, int NGUARD, int RNDA>
__global__ void __launch_bounds__(128, 2) gemm_mma(
    const float* __restrict__ A, const float* __restrict__ B,
    const float* __restrict__ bias, float* __restrict__ C,
    int K, int lda, int ldb, int ldc)
{
    constexpr int ST = 3;
    constexpr int P  = 36;                 // smem row pitch (floats)
    constexpr int ATILE = 128 * P;
    constexpr int BTILE = 128 * P;
    extern __shared__ float sm[];
    float* As = sm;
    float* Bs = sm + ST * ATILE;

    const int tid  = threadIdx.x;
    const int wid  = tid >> 5, lane = tid & 31;
    const int g    = lane >> 2, q = lane & 3;
    const int bm   = blockIdx.y * 128;
    const int bn   = blockIdx.x * 128;
    const int T    = K >> 5;
    const int mbase = (wid & 1) * 64;
    const int nbase = (wid >> 1) * 64;

    const float* Ab = A + (size_t)bm * lda + (size_t)blockIdx.z * K;
    const float* Bb = B + (size_t)bn * ldb + (size_t)blockIdx.z * K;

    auto load_tile = [&](int st, int t) {
        float* as = As + st * ATILE;
        float* bs = Bs + st * BTILE;
        #pragma unroll
        for (int i = 0; i < 8; ++i) {
            int c = tid + i * 128;
            int r = c >> 3, col = (c & 7) * 4;
            const float* src = Ab + (size_t)r * lda + t * 32 + col;
            uint32_t dst = (uint32_t)__cvta_generic_to_shared(as + r * P + col);
            asm volatile("cp.async.cg.shared.global [%0], [%1], 16;"
                         :: "r"(dst), "l"(src));
        }
        #pragma unroll
        for (int i = 0; i < 8; ++i) {
            int c = tid + i * 128;
            int r = c >> 3, col = (c & 7) * 4;
            uint32_t dst = (uint32_t)__cvta_generic_to_shared(bs + r * P + col);
            if (NGUARD && (bn + r) >= NGUARD) {
                asm volatile("cp.async.cg.shared.global [%0], [%1], 16, 0;"
                             :: "r"(dst), "l"(Bb));
            } else {
                const float* src = Bb + (size_t)r * ldb + t * 32 + col;
                asm volatile("cp.async.cg.shared.global [%0], [%1], 16;"
                             :: "r"(dst), "l"(src));
            }
        }
    };

    float c[4][8][4];
    #pragma unroll
    for (int t = 0; t < 4; ++t)
        #pragma unroll
        for (int j = 0; j < 8; ++j)
            #pragma unroll
            for (int i = 0; i < 4; ++i) c[t][j][i] = 0.f;

    #pragma unroll
    for (int s = 0; s < ST - 1; ++s) {
        if (s < T) load_tile(s, s);
        asm volatile("cp.async.commit_group;");
    }

    int cs = 0, ls = 2;
    for (int t = 0; t < T; ++t) {
        asm volatile("cp.async.wait_group 1;");
        __syncthreads();
        const float* as0 = As + cs * ATILE;
        const float* bs0 = Bs + cs * BTILE;
        #pragma unroll
        for (int k8 = 0; k8 < 4; ++k8) {
            const int k0 = k8 * 8 + q;
            uint32_t b[8][2];
            #pragma unroll
            for (int j = 0; j < 8; ++j) {
                const float* bp = bs0 + (nbase + j * 8 + g) * P + k0;
                b[j][0] = __float_as_uint(bp[0]);
                b[j][1] = __float_as_uint(bp[4]);
            }
            #pragma unroll
            for (int tt = 0; tt < 4; ++tt) {
                uint32_t a[4];
                const float* ap = as0 + (mbase + tt * 16 + g) * P + k0;
                if (RNDA) {
                    a[0] = __float_as_uint(tf32_rn(ap[0]));
                    a[1] = __float_as_uint(tf32_rn(ap[8 * P]));
                    a[2] = __float_as_uint(tf32_rn(ap[4]));
                    a[3] = __float_as_uint(tf32_rn(ap[8 * P + 4]));
                } else {
                    a[0] = __float_as_uint(ap[0]);
                    a[1] = __float_as_uint(ap[8 * P]);
                    a[2] = __float_as_uint(ap[4]);
                    a[3] = __float_as_uint(ap[8 * P + 4]);
                }
                #pragma unroll
                for (int j = 0; j < 8; ++j)
                    mma_tf32(c[tt][j], a, b[j]);
            }
        }
        const int kt = t + ST - 1;
        if (kt < T) load_tile(ls, kt);
        asm volatile("cp.async.commit_group;");
        cs = (cs == 2) ? 0 : cs + 1;
        ls = (ls == 2) ? 0 : ls + 1;
    }

    // epilogue
    #pragma unroll
    for (int tt = 0; tt < 4; ++tt) {
        const int r0 = bm + mbase + tt * 16 + g;
        #pragma unroll
        for (int j = 0; j < 8; ++j) {
            const int col = bn + nbase + j * 8 + q * 2;
            float v0 = c[tt][j][0], v1 = c[tt][j][1];
            float v2 = c[tt][j][2], v3 = c[tt][j][3];
            if (EPI == 1) {
                float b0 = bias[col], b1 = bias[col + 1];
                v0 = softplus_fast(v0 + b0);
                v1 = softplus_fast(v1 + b1);
                v2 = softplus_fast(v2 + b0);
                v3 = softplus_fast(v3 + b1);
            }
            if (EPI == 3) {
                if (!NGUARD || col < NGUARD) {
                    atomicAdd(&C[(size_t)r0 * ldc + col], v0);
                    atomicAdd(&C[(size_t)r0 * ldc + col + 1], v1);
                    atomicAdd(&C[(size_t)(r0 + 8) * ldc + col], v2);
                    atomicAdd(&C[(size_t)(r0 + 8) * ldc + col + 1], v3);
                }
            } else {
                float2 p0 = make_float2(v0, v1);
                float2 p1 = make_float2(v2, v3);
                *(float2*)&C[(size_t)r0 * ldc + col] = p0;
                *(float2*)&C[(size_t)(r0 + 8) * ldc + col] = p1;
            }
        }
    }
}

// ---------------- merged weight rounding (all 4 weights, one launch) ----------
#define WI4  (2 * DI * DM / 4)          // 1048576
#define WX4  (96 * DI / 4)              // 49152
#define WDT4 (DI * DTR / 4)             // 32768
#define WO4  (DM * DI / 4)              // 524288
__global__ void round_weights_kernel(
    const float* __restrict__ W_in, const float* __restrict__ W_x,
    const float* __restrict__ W_dt, const float* __restrict__ W_out,
    float* __restrict__ wi, float* __restrict__ wx,
    float* __restrict__ wdt, float* __restrict__ wo)
{
    int i = blockIdx.x * blockDim.x + threadIdx.x;
    const float4* src; float4* dst; int idx;
    if (i < WI4)                          { src = (const float4*)W_in;  dst = (float4*)wi;  idx = i; }
    else if (i < WI4 + WO4)               { src = (const float4*)W_out; dst = (float4*)wo;  idx = i - WI4; }
    else if (i < WI4 + WO4 + WX4)         { src = (const float4*)W_x;   dst = (float4*)wx;  idx = i - WI4 - WO4; }
    else if (i < WI4 + WO4 + WX4 + WDT4)  { src = (const float4*)W_dt;  dst = (float4*)wdt; idx = i - WI4 - WO4 - WX4; }
    else return;
    float4 v = src[idx];
    v.x = tf32_rn(v.x); v.y = tf32_rn(v.y);
    v.z = tf32_rn(v.z); v.w = tf32_rn(v.w);
    dst[idx] = v;
}

// ---------------- causal depthwise conv1d (width 4) + SiLU (+tf32) ------------
__global__ void conv_silu_kernel(const float* __restrict__ conv_w,
                                 const float* __restrict__ conv_b)
{
    int idx = blockIdx.x * blockDim.x + threadIdx.x;
    int d  = idx & (DI - 1);
    int bl = idx >> 11;
    int l  = bl & (LL - 1);
    float w0 = conv_w[d * 4 + 0], w1 = conv_w[d * 4 + 1];
    float w2 = conv_w[d * 4 + 2], w3 = conv_w[d * 4 + 3];
    const float* col = g_xr + (size_t)bl * (2 * DI) + d;
    float s = conv_b[d];
    if (l >= 3) s = fmaf(w0, col[-(3 * 2 * DI)], s);
    if (l >= 2) s = fmaf(w1, col[-(2 * 2 * DI)], s);
    if (l >= 1) s = fmaf(w2, col[-(1 * 2 * DI)], s);
    s = fmaf(w3, col[0], s);
    g_xs[idx] = tf32_rn(s / (1.f + __expf(-s)));
}

// ---------------- selective scan + D skip + gating ----------------------------
#define SC_DPB 32
#define SC_CH  64
__global__ void __launch_bounds__(256) scan_kernel(
    const float* __restrict__ A_log, const float* __restrict__ Dp)
{
    __shared__ float s_d[SC_CH][SC_DPB];
    __shared__ float s_u[SC_CH][SC_DPB];
    __shared__ float s_B[SC_CH][16];
    __shared__ float s_C[SC_CH][16];
    __shared__ float s_y[SC_CH][SC_DPB];
    const int b   = blockIdx.y;
    const int d0  = blockIdx.x * SC_DPB;
    const int tid = threadIdx.x;
    const int dl  = tid >> 3;
    const int tq  = tid & 7;
    const int d   = d0 + dl;
    const int n0  = tq * 2;

    const float LOG2E = 1.4426950408889634f;
    float a20 = -expf(A_log[d * NS + n0 + 0]) * LOG2E;
    float a21 = -expf(A_log[d * NS + n0 + 1]) * LOG2E;
    float Dv  = Dp[d];
    float h0 = 0.f, h1 = 0.f;

    for (int l0 = 0; l0 < LL; l0 += SC_CH) {
        for (int i = tid; i < SC_CH * SC_DPB; i += 256) {
            int li = i >> 5, dd = i & 31;
            size_t gg = ((size_t)(b * LL + l0 + li)) * DI + d0 + dd;
            s_d[li][dd] = g_delta[gg];
            s_u[li][dd] = g_xs[gg];
        }
        for (int i = tid; i < SC_CH * 16; i += 256) {
            int li = i >> 4, nn = i & 15;
            const float* row = g_xdbl + ((size_t)(b * LL + l0 + li)) * 96;
            s_B[li][nn] = row[64 + nn];
            s_C[li][nn] = row[80 + nn];
        }
        __syncthreads();
        #pragma unroll 4
        for (int li = 0; li < SC_CH; ++li) {
            float dv = s_d[li][dl];
            float uv = s_u[li][dl];
            float du = dv * uv;
            float dA0 = ex2_approx(dv * a20);
            float dA1 = ex2_approx(dv * a21);
            h0 = fmaf(dA0, h0, du * s_B[li][n0 + 0]);
            h1 = fmaf(dA1, h1, du * s_B[li][n0 + 1]);
            float acc = fmaf(h0, s_C[li][n0 + 0], h1 * s_C[li][n0 + 1]);
            acc += __shfl_xor_sync(0xffffffffu, acc, 1);
            acc += __shfl_xor_sync(0xffffffffu, acc, 2);
            acc += __shfl_xor_sync(0xffffffffu, acc, 4);
            if (tq == 0) s_y[li][dl] = fmaf(uv, Dv, acc);
        }
        __syncthreads();
        for (int i = tid; i < SC_CH * SC_DPB; i += 256) {
            int li = i >> 5, dd = i & 31;
            size_t bl = (size_t)(b * LL + l0 + li);
            float r  = g_xr[bl * (2 * DI) + DI + d0 + dd];
            float sr = r / (1.f + __expf(-r));
            g_yg[bl * DI + d0 + dd] = tf32_rn(s_y[li][dd] * sr);
        }
    }
}

// ---------------- launch ------------------------------------------------------
extern "C" void kernel_launch(void* const* d_in, const int* in_sizes, int n_in,
                              void* d_out, int out_size)
{
    (void)in_sizes; (void)n_in; (void)out_size;
    const float* x      = (const float*)d_in[0];
    const float* W_in   = (const float*)d_in[1];
    const float* conv_w = (const float*)d_in[2];
    const float* conv_b = (const float*)d_in[3];
    const float* W_x    = (const float*)d_in[4];
    const float* W_dt   = (const float*)d_in[5];
    const float* b_dt   = (const float*)d_in[6];
    const float* A_log  = (const float*)d_in[7];
    const float* Dp     = (const float*)d_in[8];
    const float* W_out  = (const float*)d_in[9];
    float* out = (float*)d_out;

    float *p_xr, *p_xs, *p_xdbl, *p_delta, *p_yg;
    float *p_wi, *p_wx, *p_wdt, *p_wo;
    cudaGetSymbolAddress((void**)&p_xr,    g_xr);
    cudaGetSymbolAddress((void**)&p_xs,    g_xs);
    cudaGetSymbolAddress((void**)&p_xdbl,  g_xdbl);
    cudaGetSymbolAddress((void**)&p_delta, g_delta);
    cudaGetSymbolAddress((void**)&p_yg,    g_yg);
    cudaGetSymbolAddress((void**)&p_wi,    g_wi);
    cudaGetSymbolAddress((void**)&p_wx,    g_wx);
    cudaGetSymbolAddress((void**)&p_wdt,   g_wdt);
    cudaGetSymbolAddress((void**)&p_wo,    g_wo);

    const int SMEM = 3 * (128 + 128) * 36 * 4;   // 110592 bytes -> 2 CTAs/SM
    cudaFuncSetAttribute(gemm_mma<0, 0, 1>,  cudaFuncAttributeMaxDynamicSharedMemorySize, SMEM);
    cudaFuncSetAttribute(gemm_mma<0, 0, 0>,  cudaFuncAttributeMaxDynamicSharedMemorySize, SMEM);
    cudaFuncSetAttribute(gemm_mma<1, 0, 1>,  cudaFuncAttributeMaxDynamicSharedMemorySize, SMEM);
    cudaFuncSetAttribute(gemm_mma<3, 96, 0>, cudaFuncAttributeMaxDynamicSharedMemorySize, SMEM);

    // zero the split-K accumulator
    cudaMemsetAsync(p_xdbl, 0, (size_t)NT * 96 * sizeof(float));

    // one merged TF32-RN weight rounding launch
    const int TOT4 = WI4 + WO4 + WX4 + WDT4;
    round_weights_kernel<<<(TOT4 + 255) / 256, 256>>>(
        W_in, W_x, W_dt, W_out, p_wi, p_wx, p_wdt, p_wo);

    // 1) xr = x @ W_in^T   (A = raw x, rounded in-register)
    gemm_mma<0, 0, 1><<<dim3(32, 32, 1), 128, SMEM>>>(
        x, p_wi, nullptr, p_xr, DM, DM, DM, 2 * DI);

    // 2) xs = tf32(silu(causal dwconv(xr[:, :DI])))
    conv_silu_kernel<<<(NT * DI) / 256, 256>>>(conv_w, conv_b);

    // 3) x_dbl = xs @ W_x^T  split-K=8, atomicAdd  -> [4096,96]
    gemm_mma<3, 96, 0><<<dim3(1, 32, 8), 128, SMEM>>>(
        p_xs, p_wx, nullptr, p_xdbl, DI / 8, DI, DI, 96);

    // 4) delta = fast_softplus(x_dbl[:, :64] @ W_dt^T + b_dt)  (A rounded in-reg)
    gemm_mma<1, 0, 1><<<dim3(16, 32, 1), 128, SMEM>>>(
        p_xdbl, p_wdt, b_dt, p_delta, DTR, 96, DTR, DI);

    // 5) selective scan (+D skip, *silu(res), tf32 round) -> g_yg
    scan_kernel<<<dim3(DI / SC_DPB, BB), 256>>>(A_log, Dp);

    // 6) out = yg @ W_out^T  (yg pre-rounded by scan)
    gemm_mma<0, 0, 0><<<dim3(8, 32, 1), 128, SMEM>>>(
        p_yg, p_wo, nullptr, out, DI, DI, DI, DM);
}

// round 15
// speedup vs baseline: 1.0809x; 1.0326x over previous
#include <cuda_runtime.h>
#include <math.h>
#include <stdint.h>

#define DM   1024
#define DI   2048
#define DTR  64
#define NS   16
#define BB   4
#define LL   1024
#define NT   (BB*LL)

// ---------------- scratch ----------------------------------------------------
__device__ __align__(16) float g_xr  [(size_t)NT * 2 * DI];
__device__ __align__(16) float g_xs  [(size_t)NT * DI];
__device__ __align__(16) float g_xdbl[(size_t)NT * 96];
__device__ __align__(16) float g_delta[(size_t)NT * DI];
__device__ __align__(16) float g_yg  [(size_t)NT * DI];
__device__ __align__(16) float g_wi  [(size_t)2 * DI * DM];
__device__ __align__(16) float g_wx  [(size_t)96 * DI];
__device__ __align__(16) float g_wdt [(size_t)DI * DTR];
__device__ __align__(16) float g_wo  [(size_t)DM * DI];

// ---------------- helpers -----------------------------------------------------
__device__ __forceinline__ float ex2_approx(float x) {
    float y; asm("ex2.approx.f32 %0, %1;" : "=f"(y) : "f"(x)); return y;
}
__device__ __forceinline__ float tf32_rn(float x) {
    float r; asm("cvt.rna.tf32.f32 %0, %1;" : "=f"(r) : "f"(x)); return r;
}
__device__ __forceinline__ float softplus_fast(float v) {
    return (v > 20.f) ? v : __logf(1.f + __expf(v));
}
__device__ __forceinline__ void mma_tf32(float* c, const uint32_t* a, const uint32_t* b) {
    asm volatile(
        "mma.sync.aligned.m16n8k8.row.col.f32.tf32.tf32.f32 "
        "{%0,%1,%2,%3}, {%4,%5,%6,%7}, {%8,%9}, {%0,%1,%2,%3};"
        : "+f"(c[0]), "+f"(c[1]), "+f"(c[2]), "+f"(c[3])
        : "r"(a[0]), "r"(a[1]), "r"(a[2]), "r"(a[3]), "r"(b[0]), "r"(b[1]));
}

// ---------------- TF32 mma.sync GEMM:  C[M,N] = A[M,K] * B[N,K]^T -------------
// BM=BN=128, BK=32, 3-stage cp.async, 256 threads: 8 warps of 32x64 (4M x 2N).
// smem 110.6KB -> 2 CTAs/SM => 16 warps/SM (4 per SMSP) for latency hiding.
// Low-register inner loop: hold B frags (16 regs), stream A frags 4 regs at a
// time -> mainloop fits the 128-reg cap of __launch_bounds__(256,2), no spills.
// RNDA=1: round A fragments to tf32 in-register. B (weights) pre-rounded.
// EPI: 0 none, 1 fast-softplus(x+bias[n]), 3 atomicAdd (split-K; NGUARD=valid N)
template<int EPI, int NGUARD, int RNDA>
__global__ void __launch_bounds__(256, 2) gemm_mma(
    const float* __restrict__ A, const float* __restrict__ B,
    const float* __restrict__ bias, float* __restrict__ C,
    int K, int lda, int ldb, int ldc)
{
    constexpr int ST = 3;
    constexpr int P  = 36;                 // smem row pitch (floats)
    constexpr int ATILE = 128 * P;
    constexpr int BTILE = 128 * P;
    extern __shared__ float sm[];
    float* As = sm;
    float* Bs = sm + ST * ATILE;

    const int tid  = threadIdx.x;
    const int wid  = tid >> 5, lane = tid & 31;
    const int g    = lane >> 2, q = lane & 3;
    const int bm   = blockIdx.y * 128;
    const int bn   = blockIdx.x * 128;
    const int T    = K >> 5;
    const int mbase = (wid & 3) * 32;
    const int nbase = (wid >> 2) * 64;

    const float* Ab = A + (size_t)bm * lda + (size_t)blockIdx.z * K;
    const float* Bb = B + (size_t)bn * ldb + (size_t)blockIdx.z * K;

    auto load_tile = [&](int st, int t) {
        float* as = As + st * ATILE;
        float* bs = Bs + st * BTILE;
        #pragma unroll
        for (int i = 0; i < 4; ++i) {
            int c = tid + i * 256;
            int r = c >> 3, col = (c & 7) * 4;
            const float* src = Ab + (size_t)r * lda + t * 32 + col;
            uint32_t dst = (uint32_t)__cvta_generic_to_shared(as + r * P + col);
            asm volatile("cp.async.cg.shared.global [%0], [%1], 16;"
                         :: "r"(dst), "l"(src));
        }
        #pragma unroll
        for (int i = 0; i < 4; ++i) {
            int c = tid + i * 256;
            int r = c >> 3, col = (c & 7) * 4;
            uint32_t dst = (uint32_t)__cvta_generic_to_shared(bs + r * P + col);
            if (NGUARD && (bn + r) >= NGUARD) {
                asm volatile("cp.async.cg.shared.global [%0], [%1], 16, 0;"
                             :: "r"(dst), "l"(Bb));
            } else {
                const float* src = Bb + (size_t)r * ldb + t * 32 + col;
                asm volatile("cp.async.cg.shared.global [%0], [%1], 16;"
                             :: "r"(dst), "l"(src));
            }
        }
    };

    float c[2][8][4];
    #pragma unroll
    for (int t = 0; t < 2; ++t)
        #pragma unroll
        for (int j = 0; j < 8; ++j)
            #pragma unroll
            for (int i = 0; i < 4; ++i) c[t][j][i] = 0.f;

    #pragma unroll
    for (int s = 0; s < ST - 1; ++s) {
        if (s < T) load_tile(s, s);
        asm volatile("cp.async.commit_group;");
    }

    int cs = 0, ls = 2;
    for (int t = 0; t < T; ++t) {
        asm volatile("cp.async.wait_group 1;");
        __syncthreads();
        const float* as0 = As + cs * ATILE;
        const float* bs0 = Bs + cs * BTILE;
        #pragma unroll
        for (int k8 = 0; k8 < 4; ++k8) {
            const int k0 = k8 * 8 + q;
            uint32_t b[8][2];
            #pragma unroll
            for (int j = 0; j < 8; ++j) {
                const float* bp = bs0 + (nbase + j * 8 + g) * P + k0;
                b[j][0] = __float_as_uint(bp[0]);
                b[j][1] = __float_as_uint(bp[4]);
            }
            #pragma unroll
            for (int tt = 0; tt < 2; ++tt) {
                uint32_t a[4];
                const float* ap = as0 + (mbase + tt * 16 + g) * P + k0;
                if (RNDA) {
                    a[0] = __float_as_uint(tf32_rn(ap[0]));
                    a[1] = __float_as_uint(tf32_rn(ap[8 * P]));
                    a[2] = __float_as_uint(tf32_rn(ap[4]));
                    a[3] = __float_as_uint(tf32_rn(ap[8 * P + 4]));
                } else {
                    a[0] = __float_as_uint(ap[0]);
                    a[1] = __float_as_uint(ap[8 * P]);
                    a[2] = __float_as_uint(ap[4]);
                    a[3] = __float_as_uint(ap[8 * P + 4]);
                }
                #pragma unroll
                for (int j = 0; j < 8; ++j)
                    mma_tf32(c[tt][j], a, b[j]);
            }
        }
        const int kt = t + ST - 1;
        if (kt < T) load_tile(ls, kt);
        asm volatile("cp.async.commit_group;");
        cs = (cs == 2) ? 0 : cs + 1;
        ls = (ls == 2) ? 0 : ls + 1;
    }

    // epilogue
    #pragma unroll
    for (int tt = 0; tt < 2; ++tt) {
        const int r0 = bm + mbase + tt * 16 + g;
        #pragma unroll
        for (int j = 0; j < 8; ++j) {
            const int col = bn + nbase + j * 8 + q * 2;
            float v0 = c[tt][j][0], v1 = c[tt][j][1];
            float v2 = c[tt][j][2], v3 = c[tt][j][3];
            if (EPI == 1) {
                float b0 = bias[col], b1 = bias[col + 1];
                v0 = softplus_fast(v0 + b0);
                v1 = softplus_fast(v1 + b1);
                v2 = softplus_fast(v2 + b0);
                v3 = softplus_fast(v3 + b1);
            }
            if (EPI == 3) {
                if (!NGUARD || col < NGUARD) {
                    atomicAdd(&C[(size_t)r0 * ldc + col], v0);
                    atomicAdd(&C[(size_t)r0 * ldc + col + 1], v1);
                    atomicAdd(&C[(size_t)(r0 + 8) * ldc + col], v2);
                    atomicAdd(&C[(size_t)(r0 + 8) * ldc + col + 1], v3);
                }
            } else {
                float2 p0 = make_float2(v0, v1);
                float2 p1 = make_float2(v2, v3);
                *(float2*)&C[(size_t)r0 * ldc + col] = p0;
                *(float2*)&C[(size_t)(r0 + 8) * ldc + col] = p1;
            }
        }
    }
}

// ---------------- merged weight rounding (all 4 weights, one launch) ----------
#define WI4  (2 * DI * DM / 4)
#define WX4  (96 * DI / 4)
#define WDT4 (DI * DTR / 4)
#define WO4  (DM * DI / 4)
__global__ void round_weights_kernel(
    const float* __restrict__ W_in, const float* __restrict__ W_x,
    const float* __restrict__ W_dt, const float* __restrict__ W_out,
    float* __restrict__ wi, float* __restrict__ wx,
    float* __restrict__ wdt, float* __restrict__ wo)
{
    int i = blockIdx.x * blockDim.x + threadIdx.x;
    const float4* src; float4* dst; int idx;
    if (i < WI4)                          { src = (const float4*)W_in;  dst = (float4*)wi;  idx = i; }
    else if (i < WI4 + WO4)               { src = (const float4*)W_out; dst = (float4*)wo;  idx = i - WI4; }
    else if (i < WI4 + WO4 + WX4)         { src = (const float4*)W_x;   dst = (float4*)wx;  idx = i - WI4 - WO4; }
    else if (i < WI4 + WO4 + WX4 + WDT4)  { src = (const float4*)W_dt;  dst = (float4*)wdt; idx = i - WI4 - WO4 - WX4; }
    else return;
    float4 v = src[idx];
    v.x = tf32_rn(v.x); v.y = tf32_rn(v.y);
    v.z = tf32_rn(v.z); v.w = tf32_rn(v.w);
    dst[idx] = v;
}

// ---------------- causal depthwise conv1d (width 4) + SiLU (+tf32) ------------
__global__ void conv_silu_kernel(const float* __restrict__ conv_w,
                                 const float* __restrict__ conv_b)
{
    int idx = blockIdx.x * blockDim.x + threadIdx.x;
    int d  = idx & (DI - 1);
    int bl = idx >> 11;
    int l  = bl & (LL - 1);
    float w0 = conv_w[d * 4 + 0], w1 = conv_w[d * 4 + 1];
    float w2 = conv_w[d * 4 + 2], w3 = conv_w[d * 4 + 3];
    const float* col = g_xr + (size_t)bl * (2 * DI) + d;
    float s = conv_b[d];
    if (l >= 3) s = fmaf(w0, col[-(3 * 2 * DI)], s);
    if (l >= 2) s = fmaf(w1, col[-(2 * 2 * DI)], s);
    if (l >= 1) s = fmaf(w2, col[-(1 * 2 * DI)], s);
    s = fmaf(w3, col[0], s);
    g_xs[idx] = tf32_rn(s / (1.f + __expf(-s)));
}

// ---------------- selective scan + D skip + gating ----------------------------
#define SC_DPB 32
#define SC_CH  64
__global__ void __launch_bounds__(256) scan_kernel(
    const float* __restrict__ A_log, const float* __restrict__ Dp)
{
    __shared__ float s_d[SC_CH][SC_DPB];
    __shared__ float s_u[SC_CH][SC_DPB];
    __shared__ float s_B[SC_CH][16];
    __shared__ float s_C[SC_CH][16];
    __shared__ float s_y[SC_CH][SC_DPB];
    const int b   = blockIdx.y;
    const int d0  = blockIdx.x * SC_DPB;
    const int tid = threadIdx.x;
    const int dl  = tid >> 3;
    const int tq  = tid & 7;
    const int d   = d0 + dl;
    const int n0  = tq * 2;

    const float LOG2E = 1.4426950408889634f;
    float a20 = -expf(A_log[d * NS + n0 + 0]) * LOG2E;
    float a21 = -expf(A_log[d * NS + n0 + 1]) * LOG2E;
    float Dv  = Dp[d];
    float h0 = 0.f, h1 = 0.f;

    for (int l0 = 0; l0 < LL; l0 += SC_CH) {
        for (int i = tid; i < SC_CH * SC_DPB; i += 256) {
            int li = i >> 5, dd = i & 31;
            size_t gg = ((size_t)(b * LL + l0 + li)) * DI + d0 + dd;
            s_d[li][dd] = g_delta[gg];
            s_u[li][dd] = g_xs[gg];
        }
        for (int i = tid; i < SC_CH * 16; i += 256) {
            int li = i >> 4, nn = i & 15;
            const float* row = g_xdbl + ((size_t)(b * LL + l0 + li)) * 96;
            s_B[li][nn] = row[64 + nn];
            s_C[li][nn] = row[80 + nn];
        }
        __syncthreads();
        #pragma unroll 4
        for (int li = 0; li < SC_CH; ++li) {
            float dv = s_d[li][dl];
            float uv = s_u[li][dl];
            float du = dv * uv;
            float dA0 = ex2_approx(dv * a20);
            float dA1 = ex2_approx(dv * a21);
            h0 = fmaf(dA0, h0, du * s_B[li][n0 + 0]);
            h1 = fmaf(dA1, h1, du * s_B[li][n0 + 1]);
            float acc = fmaf(h0, s_C[li][n0 + 0], h1 * s_C[li][n0 + 1]);
            acc += __shfl_xor_sync(0xffffffffu, acc, 1);
            acc += __shfl_xor_sync(0xffffffffu, acc, 2);
            acc += __shfl_xor_sync(0xffffffffu, acc, 4);
            if (tq == 0) s_y[li][dl] = fmaf(uv, Dv, acc);
        }
        __syncthreads();
        for (int i = tid; i < SC_CH * SC_DPB; i += 256) {
            int li = i >> 5, dd = i & 31;
            size_t bl = (size_t)(b * LL + l0 + li);
            float r  = g_xr[bl * (2 * DI) + DI + d0 + dd];
            float sr = r / (1.f + __expf(-r));
            g_yg[bl * DI + d0 + dd] = tf32_rn(s_y[li][dd] * sr);
        }
    }
}

// ---------------- launch ------------------------------------------------------
extern "C" void kernel_launch(void* const* d_in, const int* in_sizes, int n_in,
                              void* d_out, int out_size)
{
    (void)in_sizes; (void)n_in; (void)out_size;
    const float* x      = (const float*)d_in[0];
    const float* W_in   = (const float*)d_in[1];
    const float* conv_w = (const float*)d_in[2];
    const float* conv_b = (const float*)d_in[3];
    const float* W_x    = (const float*)d_in[4];
    const float* W_dt   = (const float*)d_in[5];
    const float* b_dt   = (const float*)d_in[6];
    const float* A_log  = (const float*)d_in[7];
    const float* Dp     = (const float*)d_in[8];
    const float* W_out  = (const float*)d_in[9];
    float* out = (float*)d_out;

    float *p_xr, *p_xs, *p_xdbl, *p_delta, *p_yg;
    float *p_wi, *p_wx, *p_wdt, *p_wo;
    cudaGetSymbolAddress((void**)&p_xr,    g_xr);
    cudaGetSymbolAddress((void**)&p_xs,    g_xs);
    cudaGetSymbolAddress((void**)&p_xdbl,  g_xdbl);
    cudaGetSymbolAddress((void**)&p_delta, g_delta);
    cudaGetSymbolAddress((void**)&p_yg,    g_yg);
    cudaGetSymbolAddress((void**)&p_wi,    g_wi);
    cudaGetSymbolAddress((void**)&p_wx,    g_wx);
    cudaGetSymbolAddress((void**)&p_wdt,   g_wdt);
    cudaGetSymbolAddress((void**)&p_wo,    g_wo);

    const int SMEM = 3 * (128 + 128) * 36 * 4;   // 110592 bytes -> 2 CTAs/SM
    cudaFuncSetAttribute(gemm_mma<0, 0, 1>,  cudaFuncAttributeMaxDynamicSharedMemorySize, SMEM);
    cudaFuncSetAttribute(gemm_mma<0, 0, 0>,  cudaFuncAttributeMaxDynamicSharedMemorySize, SMEM);
    cudaFuncSetAttribute(gemm_mma<1, 0, 1>,  cudaFuncAttributeMaxDynamicSharedMemorySize, SMEM);
    cudaFuncSetAttribute(gemm_mma<3, 96, 0>, cudaFuncAttributeMaxDynamicSharedMemorySize, SMEM);

    // zero the split-K accumulator
    cudaMemsetAsync(p_xdbl, 0, (size_t)NT * 96 * sizeof(float));

    // one merged TF32-RN weight rounding launch
    const int TOT4 = WI4 + WO4 + WX4 + WDT4;
    round_weights_kernel<<<(TOT4 + 255) / 256, 256>>>(
        W_in, W_x, W_dt, W_out, p_wi, p_wx, p_wdt, p_wo);

    // 1) xr = x @ W_in^T   (A = raw x, rounded in-register)
    gemm_mma<0, 0, 1><<<dim3(32, 32, 1), 256, SMEM>>>(
        x, p_wi, nullptr, p_xr, DM, DM, DM, 2 * DI);

    // 2) xs = tf32(silu(causal dwconv(xr[:, :DI])))
    conv_silu_kernel<<<(NT * DI) / 256, 256>>>(conv_w, conv_b);

    // 3) x_dbl = xs @ W_x^T  split-K=8, atomicAdd  -> [4096,96]
    gemm_mma<3, 96, 0><<<dim3(1, 32, 8), 256, SMEM>>>(
        p_xs, p_wx, nullptr, p_xdbl, DI / 8, DI, DI, 96);

    // 4) delta = fast_softplus(x_dbl[:, :64] @ W_dt^T + b_dt)  (A rounded in-reg)
    gemm_mma<1, 0, 1><<<dim3(16, 32, 1), 256, SMEM>>>(
        p_xdbl, p_wdt, b_dt, p_delta, DTR, 96, DTR, DI);

    // 5) selective scan (+D skip, *silu(res), tf32 round) -> g_yg
    scan_kernel<<<dim3(DI / SC_DPB, BB), 256>>>(A_log, Dp);

    // 6) out = yg @ W_out^T  (yg pre-rounded by scan)
    gemm_mma<0, 0, 0><<<dim3(8, 32, 1), 256, SMEM>>>(
        p_yg, p_wo, nullptr, out, DI, DI, DI, DM);
}

// round 16
// speedup vs baseline: 1.3489x; 1.2479x over previous
#include <cuda_runtime.h>
#include <cuda_fp16.h>
#include <math.h>
#include <stdint.h>

#define DM   1024
#define DI   2048
#define DTR  64
#define NS   16
#define BB   4
#define LL   1024
#define NT   (BB*LL)

// ---------------- scratch ----------------------------------------------------
__device__ __align__(16) float  g_xr  [(size_t)NT * 2 * DI];
__device__ __align__(16) __half g_xs  [(size_t)NT * DI];
__device__ __align__(16) float  g_xdbl[(size_t)NT * 96];
__device__ __align__(16) __half g_dth [(size_t)NT * 64];
__device__ __align__(16) float  g_delta[(size_t)NT * DI];
__device__ __align__(16) __half g_yg  [(size_t)NT * DI];
__device__ __align__(16) __half g_xh  [(size_t)NT * DM];
__device__ __align__(16) __half g_wi  [(size_t)2 * DI * DM];
__device__ __align__(16) __half g_wx  [(size_t)96 * DI];
__device__ __align__(16) __half g_wdt [(size_t)DI * DTR];
__device__ __align__(16) __half g_wo  [(size_t)DM * DI];

// ---------------- helpers -----------------------------------------------------
__device__ __forceinline__ float ex2_approx(float x) {
    float y; asm("ex2.approx.f32 %0, %1;" : "=f"(y) : "f"(x)); return y;
}
__device__ __forceinline__ float softplus_fast(float v) {
    return (v > 20.f) ? v : __logf(1.f + __expf(v));
}
__device__ __forceinline__ void mma_f16(float* c, const uint32_t* a, const uint32_t* b) {
    asm volatile(
        "mma.sync.aligned.m16n8k16.row.col.f32.f16.f16.f32 "
        "{%0,%1,%2,%3}, {%4,%5,%6,%7}, {%8,%9}, {%0,%1,%2,%3};"
        : "+f"(c[0]), "+f"(c[1]), "+f"(c[2]), "+f"(c[3])
        : "r"(a[0]), "r"(a[1]), "r"(a[2]), "r"(a[3]), "r"(b[0]), "r"(b[1]));
}
__device__ __forceinline__ void st_half4(__half* dst, float4 v) {
    __half2 h0 = __floats2half2_rn(v.x, v.y);
    __half2 h1 = __floats2half2_rn(v.z, v.w);
    uint2 u;
    u.x = *(uint32_t*)&h0;
    u.y = *(uint32_t*)&h1;
    *(uint2*)dst = u;
}

// ---------------- FP16 mma.sync GEMM:  C[M,N] = A[M,K] * B[N,K]^T -------------
// BM=BN=128, BK=32, 4-stage cp.async, 256 threads: 8 warps of 32x64 (4M x 2N).
// fp16 operand tiles, pitch 40 halves (80B, conflict-free). fp32 accumulate.
// smem 80KB -> 2 CTAs/SM (16 warps/SM). Operands pre-converted to fp16 (RNE).
// EPI: 0 none, 1 fast-softplus(x+bias[n]), 3 atomicAdd (split-K; NGUARD=valid N)
template<int EPI, int NGUARD>
__global__ void __launch_bounds__(256, 2) gemm_mma(
    const __half* __restrict__ A, const __half* __restrict__ B,
    const float* __restrict__ bias, float* __restrict__ C,
    int K, int lda, int ldb, int ldc)
{
    constexpr int ST = 4;
    constexpr int PH = 40;                    // smem row pitch (halves) = 80B
    constexpr int TILEH = 128 * PH;           // halves per stage per operand
    extern __shared__ __half smh[];
    __half* As = smh;
    __half* Bs = smh + ST * TILEH;

    const int tid  = threadIdx.x;
    const int wid  = tid >> 5, lane = tid & 31;
    const int g    = lane >> 2, q = lane & 3;
    const int bm   = blockIdx.y * 128;
    const int bn   = blockIdx.x * 128;
    const int T    = K >> 5;
    const int mbase = (wid & 3) * 32;
    const int nbase = (wid >> 2) * 64;

    const __half* Ab = A + (size_t)bm * lda + (size_t)blockIdx.z * K;
    const __half* Bb = B + (size_t)bn * ldb + (size_t)blockIdx.z * K;

    auto load_tile = [&](int st, int t) {
        __half* as = As + st * TILEH;
        __half* bs = Bs + st * TILEH;
        #pragma unroll
        for (int i = 0; i < 2; ++i) {
            int c = tid + i * 256;
            int r = c >> 2, col = (c & 3) * 8;      // 8 halves = 16B per chunk
            const __half* src = Ab + (size_t)r * lda + t * 32 + col;
            uint32_t dst = (uint32_t)__cvta_generic_to_shared(as + r * PH + col);
            asm volatile("cp.async.cg.shared.global [%0], [%1], 16;"
                         :: "r"(dst), "l"(src));
        }
        #pragma unroll
        for (int i = 0; i < 2; ++i) {
            int c = tid + i * 256;
            int r = c >> 2, col = (c & 3) * 8;
            uint32_t dst = (uint32_t)__cvta_generic_to_shared(bs + r * PH + col);
            if (NGUARD && (bn + r) >= NGUARD) {
                asm volatile("cp.async.cg.shared.global [%0], [%1], 16, 0;"
                             :: "r"(dst), "l"(Bb));
            } else {
                const __half* src = Bb + (size_t)r * ldb + t * 32 + col;
                asm volatile("cp.async.cg.shared.global [%0], [%1], 16;"
                             :: "r"(dst), "l"(src));
            }
        }
    };

    float c[2][8][4];
    #pragma unroll
    for (int t = 0; t < 2; ++t)
        #pragma unroll
        for (int j = 0; j < 8; ++j)
            #pragma unroll
            for (int i = 0; i < 4; ++i) c[t][j][i] = 0.f;

    #pragma unroll
    for (int s = 0; s < ST - 1; ++s) {
        if (s < T) load_tile(s, s);
        asm volatile("cp.async.commit_group;");
    }

    for (int t = 0; t < T; ++t) {
        asm volatile("cp.async.wait_group 2;");
        __syncthreads();
        const int st = t & 3;
        const __half* as0 = As + st * TILEH;
        const __half* bs0 = Bs + st * TILEH;
        #pragma unroll
        for (int s = 0; s < 2; ++s) {           // two m16n8k16 steps per BK=32
            const int wb = s * 8;               // word base within row
            uint32_t b[8][2];
            #pragma unroll
            for (int j = 0; j < 8; ++j) {
                const uint32_t* bp =
                    (const uint32_t*)(bs0 + (nbase + j * 8 + g) * PH);
                b[j][0] = bp[q + wb];
                b[j][1] = bp[q + 4 + wb];
            }
            #pragma unroll
            for (int tt = 0; tt < 2; ++tt) {
                const uint32_t* ap0 =
                    (const uint32_t*)(as0 + (mbase + tt * 16 + g) * PH);
                const uint32_t* ap1 =
                    (const uint32_t*)(as0 + (mbase + tt * 16 + g + 8) * PH);
                uint32_t a[4];
                a[0] = ap0[q + wb];
                a[1] = ap1[q + wb];
                a[2] = ap0[q + 4 + wb];
                a[3] = ap1[q + 4 + wb];
                #pragma unroll
                for (int j = 0; j < 8; ++j)
                    mma_f16(c[tt][j], a, b[j]);
            }
        }
        const int kt = t + ST - 1;
        if (kt < T) load_tile(kt & 3, kt);
        asm volatile("cp.async.commit_group;");
    }

    // epilogue (C fragment layout identical to tf32 m16n8k8)
    #pragma unroll
    for (int tt = 0; tt < 2; ++tt) {
        const int r0 = bm + mbase + tt * 16 + g;
        #pragma unroll
        for (int j = 0; j < 8; ++j) {
            const int col = bn + nbase + j * 8 + q * 2;
            float v0 = c[tt][j][0], v1 = c[tt][j][1];
            float v2 = c[tt][j][2], v3 = c[tt][j][3];
            if (EPI == 1) {
                float b0 = bias[col], b1 = bias[col + 1];
                v0 = softplus_fast(v0 + b0);
                v1 = softplus_fast(v1 + b1);
                v2 = softplus_fast(v2 + b0);
                v3 = softplus_fast(v3 + b1);
            }
            if (EPI == 3) {
                if (!NGUARD || col < NGUARD) {
                    atomicAdd(&C[(size_t)r0 * ldc + col], v0);
                    atomicAdd(&C[(size_t)r0 * ldc + col + 1], v1);
                    atomicAdd(&C[(size_t)(r0 + 8) * ldc + col], v2);
                    atomicAdd(&C[(size_t)(r0 + 8) * ldc + col + 1], v3);
                }
            } else {
                float2 p0 = make_float2(v0, v1);
                float2 p1 = make_float2(v2, v3);
                *(float2*)&C[(size_t)r0 * ldc + col] = p0;
                *(float2*)&C[(size_t)(r0 + 8) * ldc + col] = p1;
            }
        }
    }
}

// ---------------- merged fp32->fp16 conversion (weights + x, one launch) ------
#define X4   (NT * DM / 4)
#define WI4  (2 * DI * DM / 4)
#define WX4  (96 * DI / 4)
#define WDT4 (DI * DTR / 4)
#define WO4  (DM * DI / 4)
__global__ void convert_h_kernel(
    const float* __restrict__ x,    const float* __restrict__ W_in,
    const float* __restrict__ W_x,  const float* __restrict__ W_dt,
    const float* __restrict__ W_out,
    __half* __restrict__ xh, __half* __restrict__ wi, __half* __restrict__ wx,
    __half* __restrict__ wdt, __half* __restrict__ wo)
{
    int i = blockIdx.x * blockDim.x + threadIdx.x;
    const float4* src; __half* dst; int idx;
    if (i < X4)                                { src = (const float4*)x;     dst = xh;  idx = i; }
    else if (i < X4 + WI4)                     { src = (const float4*)W_in;  dst = wi;  idx = i - X4; }
    else if (i < X4 + WI4 + WO4)               { src = (const float4*)W_out; dst = wo;  idx = i - X4 - WI4; }
    else if (i < X4 + WI4 + WO4 + WX4)         { src = (const float4*)W_x;   dst = wx;  idx = i - X4 - WI4 - WO4; }
    else if (i < X4 + WI4 + WO4 + WX4 + WDT4)  { src = (const float4*)W_dt;  dst = wdt; idx = i - X4 - WI4 - WO4 - WX4; }
    else return;
    st_half4(dst + (size_t)idx * 4, src[idx]);
}

// ---------------- x_dbl dt-columns -> fp16 ------------------------------------
__global__ void dt_convert_kernel()
{
    int i = blockIdx.x * blockDim.x + threadIdx.x;   // over NT*32 half2
    int row = i >> 5, cp = i & 31;
    float2 v = *(const float2*)&g_xdbl[(size_t)row * 96 + cp * 2];
    *(__half2*)&g_dth[(size_t)row * 64 + cp * 2] = __floats2half2_rn(v.x, v.y);
}

// ---------------- causal depthwise conv1d (width 4) + SiLU -> fp16 ------------
__global__ void conv_silu_kernel(const float* __restrict__ conv_w,
                                 const float* __restrict__ conv_b)
{
    int idx = blockIdx.x * blockDim.x + threadIdx.x;
    int d  = idx & (DI - 1);
    int bl = idx >> 11;
    int l  = bl & (LL - 1);
    float w0 = conv_w[d * 4 + 0], w1 = conv_w[d * 4 + 1];
    float w2 = conv_w[d * 4 + 2], w3 = conv_w[d * 4 + 3];
    const float* col = g_xr + (size_t)bl * (2 * DI) + d;
    float s = conv_b[d];
    if (l >= 3) s = fmaf(w0, col[-(3 * 2 * DI)], s);
    if (l >= 2) s = fmaf(w1, col[-(2 * 2 * DI)], s);
    if (l >= 1) s = fmaf(w2, col[-(1 * 2 * DI)], s);
    s = fmaf(w3, col[0], s);
    g_xs[idx] = __float2half_rn(s / (1.f + __expf(-s)));
}

// ---------------- selective scan + D skip + gating -> fp16 yg ------------------
#define SC_DPB 32
#define SC_CH  64
__global__ void __launch_bounds__(256) scan_kernel(
    const float* __restrict__ A_log, const float* __restrict__ Dp)
{
    __shared__ float s_d[SC_CH][SC_DPB];
    __shared__ float s_u[SC_CH][SC_DPB];
    __shared__ float s_B[SC_CH][16];
    __shared__ float s_C[SC_CH][16];
    __shared__ float s_y[SC_CH][SC_DPB];
    const int b   = blockIdx.y;
    const int d0  = blockIdx.x * SC_DPB;
    const int tid = threadIdx.x;
    const int dl  = tid >> 3;
    const int tq  = tid & 7;
    const int d   = d0 + dl;
    const int n0  = tq * 2;

    const float LOG2E = 1.4426950408889634f;
    float a20 = -expf(A_log[d * NS + n0 + 0]) * LOG2E;
    float a21 = -expf(A_log[d * NS + n0 + 1]) * LOG2E;
    float Dv  = Dp[d];
    float h0 = 0.f, h1 = 0.f;

    for (int l0 = 0; l0 < LL; l0 += SC_CH) {
        for (int i = tid; i < SC_CH * SC_DPB; i += 256) {
            int li = i >> 5, dd = i & 31;
            size_t gg = ((size_t)(b * LL + l0 + li)) * DI + d0 + dd;
            s_d[li][dd] = g_delta[gg];
            s_u[li][dd] = __half2float(g_xs[gg]);
        }
        for (int i = tid; i < SC_CH * 16; i += 256) {
            int li = i >> 4, nn = i & 15;
            const float* row = g_xdbl + ((size_t)(b * LL + l0 + li)) * 96;
            s_B[li][nn] = row[64 + nn];
            s_C[li][nn] = row[80 + nn];
        }
        __syncthreads();
        #pragma unroll 4
        for (int li = 0; li < SC_CH; ++li) {
            float dv = s_d[li][dl];
            float uv = s_u[li][dl];
            float du = dv * uv;
            float dA0 = ex2_approx(dv * a20);
            float dA1 = ex2_approx(dv * a21);
            h0 = fmaf(dA0, h0, du * s_B[li][n0 + 0]);
            h1 = fmaf(dA1, h1, du * s_B[li][n0 + 1]);
            float acc = fmaf(h0, s_C[li][n0 + 0], h1 * s_C[li][n0 + 1]);
            acc += __shfl_xor_sync(0xffffffffu, acc, 1);
            acc += __shfl_xor_sync(0xffffffffu, acc, 2);
            acc += __shfl_xor_sync(0xffffffffu, acc, 4);
            if (tq == 0) s_y[li][dl] = fmaf(uv, Dv, acc);
        }
        __syncthreads();
        for (int i = tid; i < SC_CH * SC_DPB; i += 256) {
            int li = i >> 5, dd = i & 31;
            size_t bl = (size_t)(b * LL + l0 + li);
            float r  = g_xr[bl * (2 * DI) + DI + d0 + dd];
            float sr = r / (1.f + __expf(-r));
            g_yg[bl * DI + d0 + dd] = __float2half_rn(s_y[li][dd] * sr);
        }
    }
}

// ---------------- launch ------------------------------------------------------
extern "C" void kernel_launch(void* const* d_in, const int* in_sizes, int n_in,
                              void* d_out, int out_size)
{
    (void)in_sizes; (void)n_in; (void)out_size;
    const float* x      = (const float*)d_in[0];
    const float* W_in   = (const float*)d_in[1];
    const float* conv_w = (const float*)d_in[2];
    const float* conv_b = (const float*)d_in[3];
    const float* W_x    = (const float*)d_in[4];
    const float* W_dt   = (const float*)d_in[5];
    const float* b_dt   = (const float*)d_in[6];
    const float* A_log  = (const float*)d_in[7];
    const float* Dp     = (const float*)d_in[8];
    const float* W_out  = (const float*)d_in[9];
    float* out = (float*)d_out;

    float *p_xr, *p_xdbl, *p_delta;
    __half *p_xs, *p_yg, *p_xh, *p_wi, *p_wx, *p_wdt, *p_wo, *p_dth;
    cudaGetSymbolAddress((void**)&p_xr,    g_xr);
    cudaGetSymbolAddress((void**)&p_xs,    g_xs);
    cudaGetSymbolAddress((void**)&p_xdbl,  g_xdbl);
    cudaGetSymbolAddress((void**)&p_dth,   g_dth);
    cudaGetSymbolAddress((void**)&p_delta, g_delta);
    cudaGetSymbolAddress((void**)&p_yg,    g_yg);
    cudaGetSymbolAddress((void**)&p_xh,    g_xh);
    cudaGetSymbolAddress((void**)&p_wi,    g_wi);
    cudaGetSymbolAddress((void**)&p_wx,    g_wx);
    cudaGetSymbolAddress((void**)&p_wdt,   g_wdt);
    cudaGetSymbolAddress((void**)&p_wo,    g_wo);

    const int SMEM = 4 * (128 + 128) * 40 * 2;   // 81920 bytes -> 2 CTAs/SM
    cudaFuncSetAttribute(gemm_mma<0, 0>,  cudaFuncAttributeMaxDynamicSharedMemorySize, SMEM);
    cudaFuncSetAttribute(gemm_mma<1, 0>,  cudaFuncAttributeMaxDynamicSharedMemorySize, SMEM);
    cudaFuncSetAttribute(gemm_mma<3, 96>, cudaFuncAttributeMaxDynamicSharedMemorySize, SMEM);

    // zero the split-K accumulator
    cudaMemsetAsync(p_xdbl, 0, (size_t)NT * 96 * sizeof(float));

    // one merged fp32->fp16 conversion launch (x + all weights)
    const int TOT4 = X4 + WI4 + WO4 + WX4 + WDT4;
    convert_h_kernel<<<(TOT4 + 255) / 256, 256>>>(
        x, W_in, W_x, W_dt, W_out, p_xh, p_wi, p_wx, p_wdt, p_wo);

    // 1) xr = x @ W_in^T   [4096,1024]x[4096,1024]^T -> [4096,4096]
    gemm_mma<0, 0><<<dim3(32, 32, 1), 256, SMEM>>>(
        p_xh, p_wi, nullptr, p_xr, DM, DM, DM, 2 * DI);

    // 2) xs = fp16(silu(causal dwconv(xr[:, :DI])))
    conv_silu_kernel<<<(NT * DI) / 256, 256>>>(conv_w, conv_b);

    // 3) x_dbl = xs @ W_x^T  split-K=8, atomicAdd  -> [4096,96] fp32
    gemm_mma<3, 96><<<dim3(1, 32, 8), 256, SMEM>>>(
        p_xs, p_wx, nullptr, p_xdbl, DI / 8, DI, DI, 96);

    // 3b) fp16 copy of dt columns
    dt_convert_kernel<<<NT * 32 / 256, 256>>>();

    // 4) delta = fast_softplus(dth @ W_dt^T + b_dt)   K=64
    gemm_mma<1, 0><<<dim3(16, 32, 1), 256, SMEM>>>(
        p_dth, p_wdt, b_dt, p_delta, DTR, 64, DTR, DI);

    // 5) selective scan (+D skip, *silu(res)) -> g_yg fp16
    scan_kernel<<<dim3(DI / SC_DPB, BB), 256>>>(A_log, Dp);

    // 6) out = yg @ W_out^T  [4096,2048]x[1024,2048]^T -> [4096,1024]
    gemm_mma<0, 0><<<dim3(8, 32, 1), 256, SMEM>>>(
        p_yg, p_wo, nullptr, out, DI, DI, DI, DM);
}

// round 17
// speedup vs baseline: 1.4116x; 1.0465x over previous
#include <cuda_runtime.h>
#include <cuda_fp16.h>
#include <math.h>
#include <stdint.h>

#define DM   1024
#define DI   2048
#define DTR  64
#define NS   16
#define BB   4
#define LL   1024
#define NT   (BB*LL)

// ---------------- scratch ----------------------------------------------------
__device__ __align__(16) float  g_xr  [(size_t)NT * 2 * DI];
__device__ __align__(16) __half g_xs  [(size_t)NT * DI];
__device__ __align__(16) float  g_xdbl[(size_t)NT * 96];
__device__ __align__(16) __half g_dth [(size_t)NT * 64];
__device__ __align__(16) float  g_delta[(size_t)NT * DI];
__device__ __align__(16) __half g_yg  [(size_t)NT * DI];
__device__ __align__(16) __half g_xh  [(size_t)NT * DM];
__device__ __align__(16) __half g_wi  [(size_t)2 * DI * DM];
__device__ __align__(16) __half g_wx  [(size_t)96 * DI];
__device__ __align__(16) __half g_wdt [(size_t)DI * DTR];
__device__ __align__(16) __half g_wo  [(size_t)DM * DI];

// ---------------- helpers -----------------------------------------------------
__device__ __forceinline__ float ex2_approx(float x) {
    float y; asm("ex2.approx.f32 %0, %1;" : "=f"(y) : "f"(x)); return y;
}
__device__ __forceinline__ float softplus_fast(float v) {
    return (v > 20.f) ? v : __logf(1.f + __expf(v));
}
__device__ __forceinline__ void mma_f16(float* c, const uint32_t* a, const uint32_t* b) {
    asm volatile(
        "mma.sync.aligned.m16n8k16.row.col.f32.f16.f16.f32 "
        "{%0,%1,%2,%3}, {%4,%5,%6,%7}, {%8,%9}, {%0,%1,%2,%3};"
        : "+f"(c[0]), "+f"(c[1]), "+f"(c[2]), "+f"(c[3])
        : "r"(a[0]), "r"(a[1]), "r"(a[2]), "r"(a[3]), "r"(b[0]), "r"(b[1]));
}
__device__ __forceinline__ void ldsm_x4(uint32_t& r0, uint32_t& r1,
                                        uint32_t& r2, uint32_t& r3, uint32_t addr) {
    asm volatile("ldmatrix.sync.aligned.m8n8.x4.shared.b16 {%0,%1,%2,%3}, [%4];"
                 : "=r"(r0), "=r"(r1), "=r"(r2), "=r"(r3) : "r"(addr));
}
__device__ __forceinline__ void st_half4(__half* dst, float4 v) {
    __half2 h0 = __floats2half2_rn(v.x, v.y);
    __half2 h1 = __floats2half2_rn(v.z, v.w);
    uint2 u;
    u.x = *(uint32_t*)&h0;
    u.y = *(uint32_t*)&h1;
    *(uint2*)dst = u;
}

// ---------------- FP16 mma.sync GEMM:  C[M,N] = A[M,K] * B[N,K]^T -------------
// BM=BN=128, BK=32, 4-stage cp.async, 256 threads: 8 warps of 32x64 (4M x 2N).
// fp16 tiles, pitch 40 halves (80B, conflict-free for ldmatrix phases).
// Fragment loads via ldmatrix.m8n8.x4 (12 per ktile vs 48 scalar LDS).
// smem 80KB -> 2 CTAs/SM (16 warps/SM). Operands pre-converted to fp16 (RNE).
// EPI: 0 none, 1 fast-softplus(x+bias[n]), 3 atomicAdd (split-K; NGUARD=valid N)
template<int EPI, int NGUARD>
__global__ void __launch_bounds__(256, 2) gemm_mma(
    const __half* __restrict__ A, const __half* __restrict__ B,
    const float* __restrict__ bias, float* __restrict__ C,
    int K, int lda, int ldb, int ldc)
{
    constexpr int ST = 4;
    constexpr int PH = 40;                    // smem row pitch (halves) = 80B
    constexpr int TILEH = 128 * PH;           // halves per stage per operand
    extern __shared__ __half smh[];
    __half* As = smh;
    __half* Bs = smh + ST * TILEH;
    const uint32_t smb = (uint32_t)__cvta_generic_to_shared(smh);

    const int tid  = threadIdx.x;
    const int wid  = tid >> 5, lane = tid & 31;
    const int g    = lane >> 2, q = lane & 3;
    const int bm   = blockIdx.y * 128;
    const int bn   = blockIdx.x * 128;
    const int T    = K >> 5;
    const int mbase = (wid & 3) * 32;
    const int nbase = (wid >> 2) * 64;

    // ldmatrix per-lane byte offsets (within a stage tile)
    uint32_t a_off[2], b_off[4];
    {
        const int ar = lane & 15, ac = (lane >> 4) * 8;
        a_off[0] = (uint32_t)(((mbase + ar) * PH + ac) * 2);
        a_off[1] = (uint32_t)(((mbase + 16 + ar) * PH + ac) * 2);
        const int br = lane & 7, bc = ((lane >> 3) & 1) * 8, bj = (lane >> 4) & 1;
        #pragma unroll
        for (int jp = 0; jp < 4; ++jp)
            b_off[jp] = (uint32_t)(((nbase + (jp * 2 + bj) * 8 + br) * PH + bc) * 2);
    }

    const __half* Ab = A + (size_t)bm * lda + (size_t)blockIdx.z * K;
    const __half* Bb = B + (size_t)bn * ldb + (size_t)blockIdx.z * K;

    auto load_tile = [&](int st, int t) {
        __half* as = As + st * TILEH;
        __half* bs = Bs + st * TILEH;
        #pragma unroll
        for (int i = 0; i < 2; ++i) {
            int c = tid + i * 256;
            int r = c >> 2, col = (c & 3) * 8;      // 8 halves = 16B per chunk
            const __half* src = Ab + (size_t)r * lda + t * 32 + col;
            uint32_t dst = (uint32_t)__cvta_generic_to_shared(as + r * PH + col);
            asm volatile("cp.async.cg.shared.global [%0], [%1], 16;"
                         :: "r"(dst), "l"(src));
        }
        #pragma unroll
        for (int i = 0; i < 2; ++i) {
            int c = tid + i * 256;
            int r = c >> 2, col = (c & 3) * 8;
            uint32_t dst = (uint32_t)__cvta_generic_to_shared(bs + r * PH + col);
            if (NGUARD && (bn + r) >= NGUARD) {
                asm volatile("cp.async.cg.shared.global [%0], [%1], 16, 0;"
                             :: "r"(dst), "l"(Bb));
            } else {
                const __half* src = Bb + (size_t)r * ldb + t * 32 + col;
                asm volatile("cp.async.cg.shared.global [%0], [%1], 16;"
                             :: "r"(dst), "l"(src));
            }
        }
    };

    float c[2][8][4];
    #pragma unroll
    for (int t = 0; t < 2; ++t)
        #pragma unroll
        for (int j = 0; j < 8; ++j)
            #pragma unroll
            for (int i = 0; i < 4; ++i) c[t][j][i] = 0.f;

    #pragma unroll
    for (int s = 0; s < ST - 1; ++s) {
        if (s < T) load_tile(s, s);
        asm volatile("cp.async.commit_group;");
    }

    for (int t = 0; t < T; ++t) {
        asm volatile("cp.async.wait_group 2;");
        __syncthreads();
        const int st = t & 3;
        const uint32_t abase = smb + (uint32_t)(st * TILEH * 2);
        const uint32_t bbase = smb + (uint32_t)((ST + st) * TILEH * 2);
        #pragma unroll
        for (int s = 0; s < 2; ++s) {           // two m16n8k16 steps per BK=32
            const uint32_t so = (uint32_t)(s * 32);   // 16 halves = 32 bytes
            uint32_t b[8][2];
            #pragma unroll
            for (int jp = 0; jp < 4; ++jp)
                ldsm_x4(b[jp * 2][0], b[jp * 2][1], b[jp * 2 + 1][0], b[jp * 2 + 1][1],
                        bbase + b_off[jp] + so);
            uint32_t a[2][4];
            #pragma unroll
            for (int tt = 0; tt < 2; ++tt)
                ldsm_x4(a[tt][0], a[tt][1], a[tt][2], a[tt][3],
                        abase + a_off[tt] + so);
            #pragma unroll
            for (int tt = 0; tt < 2; ++tt)
                #pragma unroll
                for (int j = 0; j < 8; ++j)
                    mma_f16(c[tt][j], a[tt], b[j]);
        }
        const int kt = t + ST - 1;
        if (kt < T) load_tile(kt & 3, kt);
        asm volatile("cp.async.commit_group;");
    }

    // epilogue (C fragment layout identical across tf32/fp16 mma)
    #pragma unroll
    for (int tt = 0; tt < 2; ++tt) {
        const int r0 = bm + mbase + tt * 16 + g;
        #pragma unroll
        for (int j = 0; j < 8; ++j) {
            const int col = bn + nbase + j * 8 + q * 2;
            float v0 = c[tt][j][0], v1 = c[tt][j][1];
            float v2 = c[tt][j][2], v3 = c[tt][j][3];
            if (EPI == 1) {
                float b0 = bias[col], b1 = bias[col + 1];
                v0 = softplus_fast(v0 + b0);
                v1 = softplus_fast(v1 + b1);
                v2 = softplus_fast(v2 + b0);
                v3 = softplus_fast(v3 + b1);
            }
            if (EPI == 3) {
                if (!NGUARD || col < NGUARD) {
                    atomicAdd(&C[(size_t)r0 * ldc + col], v0);
                    atomicAdd(&C[(size_t)r0 * ldc + col + 1], v1);
                    atomicAdd(&C[(size_t)(r0 + 8) * ldc + col], v2);
                    atomicAdd(&C[(size_t)(r0 + 8) * ldc + col + 1], v3);
                }
            } else {
                float2 p0 = make_float2(v0, v1);
                float2 p1 = make_float2(v2, v3);
                *(float2*)&C[(size_t)r0 * ldc + col] = p0;
                *(float2*)&C[(size_t)(r0 + 8) * ldc + col] = p1;
            }
        }
    }
}

// ---------------- merged fp32->fp16 conversion (weights + x, one launch) ------
#define X4   (NT * DM / 4)
#define WI4  (2 * DI * DM / 4)
#define WX4  (96 * DI / 4)
#define WDT4 (DI * DTR / 4)
#define WO4  (DM * DI / 4)
__global__ void convert_h_kernel(
    const float* __restrict__ x,    const float* __restrict__ W_in,
    const float* __restrict__ W_x,  const float* __restrict__ W_dt,
    const float* __restrict__ W_out,
    __half* __restrict__ xh, __half* __restrict__ wi, __half* __restrict__ wx,
    __half* __restrict__ wdt, __half* __restrict__ wo)
{
    int i = blockIdx.x * blockDim.x + threadIdx.x;
    const float4* src; __half* dst; int idx;
    if (i < X4)                                { src = (const float4*)x;     dst = xh;  idx = i; }
    else if (i < X4 + WI4)                     { src = (const float4*)W_in;  dst = wi;  idx = i - X4; }
    else if (i < X4 + WI4 + WO4)               { src = (const float4*)W_out; dst = wo;  idx = i - X4 - WI4; }
    else if (i < X4 + WI4 + WO4 + WX4)         { src = (const float4*)W_x;   dst = wx;  idx = i - X4 - WI4 - WO4; }
    else if (i < X4 + WI4 + WO4 + WX4 + WDT4)  { src = (const float4*)W_dt;  dst = wdt; idx = i - X4 - WI4 - WO4 - WX4; }
    else return;
    st_half4(dst + (size_t)idx * 4, src[idx]);
}

// ---------------- x_dbl dt-columns -> fp16 ------------------------------------
__global__ void dt_convert_kernel()
{
    int i = blockIdx.x * blockDim.x + threadIdx.x;   // over NT*32 half2
    int row = i >> 5, cp = i & 31;
    float2 v = *(const float2*)&g_xdbl[(size_t)row * 96 + cp * 2];
    *(__half2*)&g_dth[(size_t)row * 64 + cp * 2] = __floats2half2_rn(v.x, v.y);
}

// ---------------- causal depthwise conv1d (width 4) + SiLU -> fp16 ------------
__global__ void conv_silu_kernel(const float* __restrict__ conv_w,
                                 const float* __restrict__ conv_b)
{
    int idx = blockIdx.x * blockDim.x + threadIdx.x;
    int d  = idx & (DI - 1);
    int bl = idx >> 11;
    int l  = bl & (LL - 1);
    float w0 = conv_w[d * 4 + 0], w1 = conv_w[d * 4 + 1];
    float w2 = conv_w[d * 4 + 2], w3 = conv_w[d * 4 + 3];
    const float* col = g_xr + (size_t)bl * (2 * DI) + d;
    float s = conv_b[d];
    if (l >= 3) s = fmaf(w0, col[-(3 * 2 * DI)], s);
    if (l >= 2) s = fmaf(w1, col[-(2 * 2 * DI)], s);
    if (l >= 1) s = fmaf(w2, col[-(1 * 2 * DI)], s);
    s = fmaf(w3, col[0], s);
    g_xs[idx] = __float2half_rn(s / (1.f + __expf(-s)));
}

// ---------------- selective scan + D skip + gating -> fp16 yg ------------------
#define SC_DPB 32
#define SC_CH  64
__global__ void __launch_bounds__(256) scan_kernel(
    const float* __restrict__ A_log, const float* __restrict__ Dp)
{
    __shared__ float s_d[SC_CH][SC_DPB];
    __shared__ float s_u[SC_CH][SC_DPB];
    __shared__ float s_B[SC_CH][16];
    __shared__ float s_C[SC_CH][16];
    __shared__ float s_y[SC_CH][SC_DPB];
    const int b   = blockIdx.y;
    const int d0  = blockIdx.x * SC_DPB;
    const int tid = threadIdx.x;
    const int dl  = tid >> 3;
    const int tq  = tid & 7;
    const int d   = d0 + dl;
    const int n0  = tq * 2;

    const float LOG2E = 1.4426950408889634f;
    float a20 = -expf(A_log[d * NS + n0 + 0]) * LOG2E;
    float a21 = -expf(A_log[d * NS + n0 + 1]) * LOG2E;
    float Dv  = Dp[d];
    float h0 = 0.f, h1 = 0.f;

    for (int l0 = 0; l0 < LL; l0 += SC_CH) {
        for (int i = tid; i < SC_CH * SC_DPB; i += 256) {
            int li = i >> 5, dd = i & 31;
            size_t gg = ((size_t)(b * LL + l0 + li)) * DI + d0 + dd;
            s_d[li][dd] = g_delta[gg];
            s_u[li][dd] = __half2float(g_xs[gg]);
        }
        for (int i = tid; i < SC_CH * 16; i += 256) {
            int li = i >> 4, nn = i & 15;
            const float* row = g_xdbl + ((size_t)(b * LL + l0 + li)) * 96;
            s_B[li][nn] = row[64 + nn];
            s_C[li][nn] = row[80 + nn];
        }
        __syncthreads();
        #pragma unroll 4
        for (int li = 0; li < SC_CH; ++li) {
            float dv = s_d[li][dl];
            float uv = s_u[li][dl];
            float du = dv * uv;
            float dA0 = ex2_approx(dv * a20);
            float dA1 = ex2_approx(dv * a21);
            h0 = fmaf(dA0, h0, du * s_B[li][n0 + 0]);
            h1 = fmaf(dA1, h1, du * s_B[li][n0 + 1]);
            float acc = fmaf(h0, s_C[li][n0 + 0], h1 * s_C[li][n0 + 1]);
            acc += __shfl_xor_sync(0xffffffffu, acc, 1);
            acc += __shfl_xor_sync(0xffffffffu, acc, 2);
            acc += __shfl_xor_sync(0xffffffffu, acc, 4);
            if (tq == 0) s_y[li][dl] = fmaf(uv, Dv, acc);
        }
        __syncthreads();
        for (int i = tid; i < SC_CH * SC_DPB; i += 256) {
            int li = i >> 5, dd = i & 31;
            size_t bl = (size_t)(b * LL + l0 + li);
            float r  = g_xr[bl * (2 * DI) + DI + d0 + dd];
            float sr = r / (1.f + __expf(-r));
            g_yg[bl * DI + d0 + dd] = __float2half_rn(s_y[li][dd] * sr);
        }
    }
}

// ---------------- launch ------------------------------------------------------
extern "C" void kernel_launch(void* const* d_in, const int* in_sizes, int n_in,
                              void* d_out, int out_size)
{
    (void)in_sizes; (void)n_in; (void)out_size;
    const float* x      = (const float*)d_in[0];
    const float* W_in   = (const float*)d_in[1];
    const float* conv_w = (const float*)d_in[2];
    const float* conv_b = (const float*)d_in[3];
    const float* W_x    = (const float*)d_in[4];
    const float* W_dt   = (const float*)d_in[5];
    const float* b_dt   = (const float*)d_in[6];
    const float* A_log  = (const float*)d_in[7];
    const float* Dp     = (const float*)d_in[8];
    const float* W_out  = (const float*)d_in[9];
    float* out = (float*)d_out;

    float *p_xr, *p_xdbl, *p_delta;
    __half *p_xs, *p_yg, *p_xh, *p_wi, *p_wx, *p_wdt, *p_wo, *p_dth;
    cudaGetSymbolAddress((void**)&p_xr,    g_xr);
    cudaGetSymbolAddress((void**)&p_xs,    g_xs);
    cudaGetSymbolAddress((void**)&p_xdbl,  g_xdbl);
    cudaGetSymbolAddress((void**)&p_dth,   g_dth);
    cudaGetSymbolAddress((void**)&p_delta, g_delta);
    cudaGetSymbolAddress((void**)&p_yg,    g_yg);
    cudaGetSymbolAddress((void**)&p_xh,    g_xh);
    cudaGetSymbolAddress((void**)&p_wi,    g_wi);
    cudaGetSymbolAddress((void**)&p_wx,    g_wx);
    cudaGetSymbolAddress((void**)&p_wdt,   g_wdt);
    cudaGetSymbolAddress((void**)&p_wo,    g_wo);

    const int SMEM = 4 * (128 + 128) * 40 * 2;   // 81920 bytes -> 2 CTAs/SM
    cudaFuncSetAttribute(gemm_mma<0, 0>,  cudaFuncAttributeMaxDynamicSharedMemorySize, SMEM);
    cudaFuncSetAttribute(gemm_mma<1, 0>,  cudaFuncAttributeMaxDynamicSharedMemorySize, SMEM);
    cudaFuncSetAttribute(gemm_mma<3, 96>, cudaFuncAttributeMaxDynamicSharedMemorySize, SMEM);

    // zero the split-K accumulator
    cudaMemsetAsync(p_xdbl, 0, (size_t)NT * 96 * sizeof(float));

    // one merged fp32->fp16 conversion launch (x + all weights)
    const int TOT4 = X4 + WI4 + WO4 + WX4 + WDT4;
    convert_h_kernel<<<(TOT4 + 255) / 256, 256>>>(
        x, W_in, W_x, W_dt, W_out, p_xh, p_wi, p_wx, p_wdt, p_wo);

    // 1) xr = x @ W_in^T   [4096,1024]x[4096,1024]^T -> [4096,4096]
    gemm_mma<0, 0><<<dim3(32, 32, 1), 256, SMEM>>>(
        p_xh, p_wi, nullptr, p_xr, DM, DM, DM, 2 * DI);

    // 2) xs = fp16(silu(causal dwconv(xr[:, :DI])))
    conv_silu_kernel<<<(NT * DI) / 256, 256>>>(conv_w, conv_b);

    // 3) x_dbl = xs @ W_x^T  split-K=8, atomicAdd  -> [4096,96] fp32
    gemm_mma<3, 96><<<dim3(1, 32, 8), 256, SMEM>>>(
        p_xs, p_wx, nullptr, p_xdbl, DI / 8, DI, DI, 96);

    // 3b) fp16 copy of dt columns
    dt_convert_kernel<<<NT * 32 / 256, 256>>>();

    // 4) delta = fast_softplus(dth @ W_dt^T + b_dt)   K=64
    gemm_mma<1, 0><<<dim3(16, 32, 1), 256, SMEM>>>(
        p_dth, p_wdt, b_dt, p_delta, DTR, 64, DTR, DI);

    // 5) selective scan (+D skip, *silu(res)) -> g_yg fp16
    scan_kernel<<<dim3(DI / SC_DPB, BB), 256>>>(A_log, Dp);

    // 6) out = yg @ W_out^T  [4096,2048]x[1024,2048]^T -> [4096,1024]
    gemm_mma<0, 0><<<dim3(8, 32, 1), 256, SMEM>>>(
        p_yg, p_wo, nullptr, out, DI, DI, DI, DM);
}